// round 6
// baseline (speedup 1.0000x reference)
#include <cuda_runtime.h>
#include <cuda_bf16.h>
#include <cstdint>

// ---------------------------------------------------------------------------
// MeshRefineNet on GB300 (sm_103a), R6: fully fused layers (R5 + bugfix in
// final_fused_kernel smem weight load bound: 384 -> 512).
// Identity used:  agg_i = sum_j (x_j@W1 + b1) = (sum_j x_j)@W1 + deg_i*b1
// So each layer = ONE persistent kernel:
//   per 32-node tile: stage A = [x | S] (K=256, S = gathered neighbor sum),
//   HMMA split-bf16 (Ahi@Bhi + Ahi@Blo + Alo@Bhi), epilogue adds b0+deg*b1.
// Layer2 epilogue writes h = relu(out)+features. Final layer = fused
// gather + 128->3 dot kernel. No h1 buffer, no separate gather kernels.
// ---------------------------------------------------------------------------

#define NMAX 320000
#define EMAX 1000000

__device__ float g_bufA[NMAX * 128];
__device__ float g_bufB[NMAX * 128];

// pre-split weight images: Bt[n][k], n in [0,128) outputs, k in [0,256)
// (k<128 -> W0[k][n], k>=128 -> W1[k-128][n]); hi/lo bf16, linear u32 pairs.
__device__ __align__(16) __nv_bfloat16 g_Whi[3][128 * 256];
__device__ __align__(16) __nv_bfloat16 g_Wlo[3][128 * 256];
__device__ float g_bias[3][256];           // [0:128) b0, [128:256) b1

// CSR scratch
__device__ int g_deg[NMAX];
__device__ int g_cur[NMAX];
__device__ int g_rowstart[NMAX + 1];
__device__ int g_adj[2 * EMAX];
__device__ int g_bsum[512];

// ======================= helpers ===========================================
__device__ __forceinline__ uint32_t smem_to_u32(const void* p) {
    uint32_t a;
    asm("{ .reg .u64 t; cvta.to.shared.u64 t, %1; cvt.u32.u64 %0, t; }"
        : "=r"(a) : "l"(p));
    return a;
}
__device__ __forceinline__ uint32_t pkbf(float a, float b) {
    __nv_bfloat162 t = __floats2bfloat162_rn(a, b);
    return *(uint32_t*)&t;
}
// XOR swizzle for 512B rows (256 halves = 32 16B-blocks per row)
__device__ __forceinline__ uint32_t aswz2(uint32_t row, uint32_t kb) {
    return (row << 9) + (((((kb) ^ row) & 7u) | (kb & 24u)) << 4);
}
__device__ __forceinline__ void ldsm_x4(uint32_t& r0, uint32_t& r1,
                                        uint32_t& r2, uint32_t& r3, uint32_t addr) {
    asm volatile("ldmatrix.sync.aligned.m8n8.x4.shared.b16 {%0,%1,%2,%3}, [%4];"
                 : "=r"(r0), "=r"(r1), "=r"(r2), "=r"(r3) : "r"(addr));
}
__device__ __forceinline__ void mma16816(float* d, const uint32_t* a,
                                         const uint32_t* b) {
    asm volatile("mma.sync.aligned.m16n8k16.row.col.f32.bf16.bf16.f32 "
                 "{%0,%1,%2,%3}, {%4,%5,%6,%7}, {%8,%9}, {%0,%1,%2,%3};"
                 : "+f"(d[0]), "+f"(d[1]), "+f"(d[2]), "+f"(d[3])
                 : "r"(a[0]), "r"(a[1]), "r"(a[2]), "r"(a[3]),
                   "r"(b[0]), "r"(b[1]));
}
__device__ __forceinline__ float4 relu4(float4 v) {
    v.x = fmaxf(v.x, 0.f); v.y = fmaxf(v.y, 0.f);
    v.z = fmaxf(v.z, 0.f); v.w = fmaxf(v.w, 0.f);
    return v;
}

// ======================= weight prep (once per launch) =====================
__global__ void prep_w_kernel(const float* __restrict__ W0, const float* __restrict__ b0,
                              const float* __restrict__ W1, const float* __restrict__ b1,
                              __nv_bfloat16* __restrict__ hi, __nv_bfloat16* __restrict__ lo,
                              float* __restrict__ biasOut)
{
    int t0 = blockIdx.x * blockDim.x + threadIdx.x;
    if (t0 < 128) { biasOut[t0] = b0[t0]; biasOut[128 + t0] = b1[t0]; }
    uint32_t* hip = (uint32_t*)hi;
    uint32_t* lop = (uint32_t*)lo;
    for (int idx = t0; idx < 128 * 128; idx += blockDim.x * gridDim.x) {
        int n = idx >> 7, p = idx & 127;       // p = u32 pair index, k = 2p
        int k = p * 2;
        float x0 = (k < 128)     ? W0[k * 128 + n]       : W1[(k - 128) * 128 + n];
        float x1 = (k + 1 < 128) ? W0[(k + 1) * 128 + n] : W1[(k + 1 - 128) * 128 + n];
        float h0f = __bfloat162float(__float2bfloat16_rn(x0));
        float h1f = __bfloat162float(__float2bfloat16_rn(x1));
        hip[idx] = pkbf(x0, x1);
        lop[idx] = pkbf(x0 - h0f, x1 - h1f);
    }
}

// ======================= CSR build =========================================
__global__ void zero_deg_kernel(int* deg, int n) {
    int i = blockIdx.x * blockDim.x + threadIdx.x;
    if (i < n) deg[i] = 0;
}
__global__ void count_deg_kernel(const int2* __restrict__ edges, int* deg, int E) {
    int e = blockIdx.x * blockDim.x + threadIdx.x;
    if (e >= E) return;
    int2 ed = __ldg(&edges[e]);
    atomicAdd(&deg[ed.x], 1);
    atomicAdd(&deg[ed.y], 1);
}
__global__ __launch_bounds__(1024)
void scanA_kernel(const int* __restrict__ deg, int* rowstart, int* bsum, int n) {
    __shared__ int s[1024];
    int t = threadIdx.x;
    int i = blockIdx.x * 1024 + t;
    int v = (i < n) ? deg[i] : 0;
    s[t] = v;
    __syncthreads();
#pragma unroll
    for (int o = 1; o < 1024; o <<= 1) {
        int x = (t >= o) ? s[t - o] : 0;
        __syncthreads();
        s[t] += x;
        __syncthreads();
    }
    if (i < n) rowstart[i] = s[t] - v;
    if (t == 1023) bsum[blockIdx.x] = s[1023];
}
__global__ __launch_bounds__(512)
void scanB_kernel(int* bsum, int nb) {
    __shared__ int s[512];
    int t = threadIdx.x;
    int v = (t < nb) ? bsum[t] : 0;
    s[t] = v;
    __syncthreads();
#pragma unroll
    for (int o = 1; o < 512; o <<= 1) {
        int x = (t >= o) ? s[t - o] : 0;
        __syncthreads();
        s[t] += x;
        __syncthreads();
    }
    if (t < nb) bsum[t] = s[t] - v;
}
__global__ __launch_bounds__(1024)
void scanC_kernel(int* rowstart, int* cur, const int* __restrict__ bsum,
                  int n, int total) {
    int i = blockIdx.x * 1024 + threadIdx.x;
    if (i < n) {
        int r = rowstart[i] + bsum[blockIdx.x];
        rowstart[i] = r;
        cur[i] = r;
    }
    if (i == 0) rowstart[n] = total;
}
__global__ void fill_adj_kernel(const int2* __restrict__ edges, int* cur,
                                int* adj, int E) {
    int e = blockIdx.x * blockDim.x + threadIdx.x;
    if (e >= E) return;
    int2 ed = __ldg(&edges[e]);
    int ps = atomicAdd(&cur[ed.x], 1);
    adj[ps] = ed.y;
    int pd = atomicAdd(&cur[ed.y], 1);
    adj[pd] = ed.x;
}

// ======================= fused persistent layer kernel =====================
// smem: B_hi 64K | B_lo 64K | A dbuf 2 x (hi 16K + lo 16K) = 192 KB total.
static constexpr int SM_B_HI = 0;
static constexpr int SM_B_LO = 65536;
static constexpr int SM_A    = 131072;
static constexpr int A_STRIDE = 32768;     // per buffer
static constexpr int A_LO     = 16384;     // lo offset within buffer
static constexpr int SM_DYN  = 196608;

// IN_RELU: relu on both own row and gathered neighbors (layer input transform)
// EPI: 0 = out = v + b0 + deg*b1 ; 1 = out = relu(v + b0 + deg*b1) + feat
template<int IN_RELU, int EPI>
__global__ __launch_bounds__(512, 1)
void layer_fused_kernel(const float* __restrict__ in,
                        const float* __restrict__ feat,
                        const __nv_bfloat16* __restrict__ Whi,
                        const __nv_bfloat16* __restrict__ Wlo,
                        const float* __restrict__ bias256,
                        const int* __restrict__ rowstart,
                        const int* __restrict__ adj,
                        const int* __restrict__ deg,
                        float* __restrict__ out,
                        int n, int numTiles)
{
    extern __shared__ char sm[];
    const uint32_t sbase = smem_to_u32(sm);
    const int tid  = threadIdx.x;
    const int wid  = tid >> 5;
    const int lane = tid & 31;

    // ---- stage B hi/lo once (swizzled 512B rows) ----
    {
        const uint32_t* srcH = (const uint32_t*)Whi;
        const uint32_t* srcL = (const uint32_t*)Wlo;
#pragma unroll
        for (int u = 0; u < 32; u++) {
            int idx = u * 512 + tid;            // 0..16383
            int row = idx >> 7, p = idx & 127;  // p = u32 index in row
            uint32_t off = aswz2(row, p >> 2) + (p & 3) * 4;
            *(uint32_t*)(sm + SM_B_HI + off) = srcH[idx];
            *(uint32_t*)(sm + SM_B_LO + off) = srcL[idx];
        }
    }

    int tile = blockIdx.x;
    if (tile >= numTiles) { __syncthreads(); return; }

    // MMA geometry: warp grid 2(m) x 8(n), warp tile 16x16
    const int mbase = (wid & 1) * 16;
    const int nbase = (wid >> 1) * 16;
    const int aRow  = lane & 15;
    const int aKs   = lane >> 4;
    const int bTile = lane >> 3;
    const int bRow  = (lane & 7) + ((bTile >> 1) << 3);
    const int bKs   = bTile & 1;

    // ---- stage tile0 into buf 0 -------------------------------------------
    {
        const int tb = tile * 32;
        char* ab = sm + SM_A;                  // buf 0
        // x part: 32 rows x 128 floats
#pragma unroll
        for (int u = 0; u < 4; u++) {
            int idx = u * 512 + tid;           // 0..2047 float2 slots
            int row = idx >> 6, p = idx & 63;  // p = u32 idx (k pair)
            int gr = tb + row;
            float2 xv = (gr < n) ? *(const float2*)(in + (size_t)gr * 128 + p * 2)
                                 : make_float2(0.f, 0.f);
            if (IN_RELU) { xv.x = fmaxf(xv.x, 0.f); xv.y = fmaxf(xv.y, 0.f); }
            float hx = __bfloat162float(__float2bfloat16_rn(xv.x));
            float hy = __bfloat162float(__float2bfloat16_rn(xv.y));
            uint32_t off = aswz2(row, p >> 2) + (p & 3) * 4;
            *(uint32_t*)(ab + off)        = pkbf(xv.x, xv.y);
            *(uint32_t*)(ab + A_LO + off) = pkbf(xv.x - hx, xv.y - hy);
        }
        // gather part: warp handles 2 nodes; lane covers k = lane*4..+3
#pragma unroll
        for (int s2 = 0; s2 < 2; s2++) {
            int lr = wid * 2 + s2;
            int nd = tb + lr;
            float4 acc = make_float4(0.f, 0.f, 0.f, 0.f);
            if (nd < n) {
                int rs = __ldg(&rowstart[nd]);
                int re = __ldg(&rowstart[nd + 1]);
                int e = rs;
                for (; e + 3 < re; e += 4) {
                    int j0 = __ldg(&adj[e]),     j1 = __ldg(&adj[e + 1]);
                    int j2 = __ldg(&adj[e + 2]), j3 = __ldg(&adj[e + 3]);
                    float4 v0 = __ldg((const float4*)(in + (size_t)j0 * 128 + lane * 4));
                    float4 v1 = __ldg((const float4*)(in + (size_t)j1 * 128 + lane * 4));
                    float4 v2 = __ldg((const float4*)(in + (size_t)j2 * 128 + lane * 4));
                    float4 v3 = __ldg((const float4*)(in + (size_t)j3 * 128 + lane * 4));
                    if (IN_RELU) { v0 = relu4(v0); v1 = relu4(v1); v2 = relu4(v2); v3 = relu4(v3); }
                    acc.x += v0.x + v1.x + v2.x + v3.x;
                    acc.y += v0.y + v1.y + v2.y + v3.y;
                    acc.z += v0.z + v1.z + v2.z + v3.z;
                    acc.w += v0.w + v1.w + v2.w + v3.w;
                }
                for (; e < re; e++) {
                    int j = __ldg(&adj[e]);
                    float4 v = __ldg((const float4*)(in + (size_t)j * 128 + lane * 4));
                    if (IN_RELU) v = relu4(v);
                    acc.x += v.x; acc.y += v.y; acc.z += v.z; acc.w += v.w;
                }
            }
            uint32_t p0 = 64 + lane * 2;       // u32 idx in [64,128)
            float hx = __bfloat162float(__float2bfloat16_rn(acc.x));
            float hy = __bfloat162float(__float2bfloat16_rn(acc.y));
            float hz = __bfloat162float(__float2bfloat16_rn(acc.z));
            float hw = __bfloat162float(__float2bfloat16_rn(acc.w));
            uint32_t off0 = aswz2(lr, p0 >> 2) + (p0 & 3) * 4;
            uint32_t off1 = aswz2(lr, (p0 + 1) >> 2) + ((p0 + 1) & 3) * 4;
            *(uint32_t*)(ab + off0)        = pkbf(acc.x, acc.y);
            *(uint32_t*)(ab + A_LO + off0) = pkbf(acc.x - hx, acc.y - hy);
            *(uint32_t*)(ab + off1)        = pkbf(acc.z, acc.w);
            *(uint32_t*)(ab + A_LO + off1) = pkbf(acc.z - hz, acc.w - hw);
        }
    }
    __syncthreads();

    int buf = 0;
    for (;;) {
        const int tb = tile * 32;
        const int next = tile + gridDim.x;
        const bool hasNext = next < numTiles;

        // ---- prefetch next tile into registers (loads overlap MMA) --------
        float2 xr[4];
        float4 ga[2];
        if (hasNext) {
            const int tb2 = next * 32;
#pragma unroll
            for (int u = 0; u < 4; u++) {
                int idx = u * 512 + tid;
                int row = idx >> 6, p = idx & 63;
                int gr = tb2 + row;
                xr[u] = (gr < n) ? *(const float2*)(in + (size_t)gr * 128 + p * 2)
                                 : make_float2(0.f, 0.f);
            }
#pragma unroll
            for (int s2 = 0; s2 < 2; s2++) {
                int nd = tb2 + wid * 2 + s2;
                float4 acc = make_float4(0.f, 0.f, 0.f, 0.f);
                if (nd < n) {
                    int rs = __ldg(&rowstart[nd]);
                    int re = __ldg(&rowstart[nd + 1]);
                    int e = rs;
                    for (; e + 3 < re; e += 4) {
                        int j0 = __ldg(&adj[e]),     j1 = __ldg(&adj[e + 1]);
                        int j2 = __ldg(&adj[e + 2]), j3 = __ldg(&adj[e + 3]);
                        float4 v0 = __ldg((const float4*)(in + (size_t)j0 * 128 + lane * 4));
                        float4 v1 = __ldg((const float4*)(in + (size_t)j1 * 128 + lane * 4));
                        float4 v2 = __ldg((const float4*)(in + (size_t)j2 * 128 + lane * 4));
                        float4 v3 = __ldg((const float4*)(in + (size_t)j3 * 128 + lane * 4));
                        if (IN_RELU) { v0 = relu4(v0); v1 = relu4(v1); v2 = relu4(v2); v3 = relu4(v3); }
                        acc.x += v0.x + v1.x + v2.x + v3.x;
                        acc.y += v0.y + v1.y + v2.y + v3.y;
                        acc.z += v0.z + v1.z + v2.z + v3.z;
                        acc.w += v0.w + v1.w + v2.w + v3.w;
                    }
                    for (; e < re; e++) {
                        int j = __ldg(&adj[e]);
                        float4 v = __ldg((const float4*)(in + (size_t)j * 128 + lane * 4));
                        if (IN_RELU) v = relu4(v);
                        acc.x += v.x; acc.y += v.y; acc.z += v.z; acc.w += v.w;
                    }
                }
                ga[s2] = acc;
            }
        }

        // ---- MMA on current buffer (K=256, 3 splits) ----------------------
        float d[2][4];
#pragma unroll
        for (int nh = 0; nh < 2; nh++)
#pragma unroll
            for (int q = 0; q < 4; q++) d[nh][q] = 0.f;

        const uint32_t abufB = sbase + SM_A + buf * A_STRIDE;
#pragma unroll
        for (int s = 0; s < 3; s++) {
            const uint32_t aB = abufB + ((s == 2) ? A_LO : 0);
            const uint32_t bB = sbase + ((s == 1) ? SM_B_LO : SM_B_HI);
#pragma unroll
            for (int kk = 0; kk < 16; kk++) {
                const int kb0 = kk * 2;
                uint32_t a[4];
                ldsm_x4(a[0], a[1], a[2], a[3], aB + aswz2(mbase + aRow, kb0 + aKs));
                uint32_t b0, b1, b2, b3;
                ldsm_x4(b0, b1, b2, b3, bB + aswz2(nbase + bRow, kb0 + bKs));
                uint32_t blo[2] = {b0, b1};
                uint32_t bhi[2] = {b2, b3};
                mma16816(d[0], a, blo);
                mma16816(d[1], a, bhi);
            }
        }

        // ---- epilogue: +b0 + deg*b1 (EPI=1: relu + feat skip) -------------
        {
            int r0 = tb + mbase + (lane >> 2);
            int colBase = nbase + 2 * (lane & 3);
#pragma unroll
            for (int h = 0; h < 2; h++) {
                int row = r0 + h * 8;
                if (row >= n) continue;
                float dg = (float)__ldg(&deg[row]);
#pragma unroll
                for (int nh = 0; nh < 2; nh++) {
                    int col = colBase + nh * 8;
                    float2 b0v = __ldg((const float2*)(bias256 + col));
                    float2 b1v = __ldg((const float2*)(bias256 + 128 + col));
                    float2 v;
                    v.x = d[nh][2 * h + 0] + b0v.x + dg * b1v.x;
                    v.y = d[nh][2 * h + 1] + b0v.y + dg * b1v.y;
                    if (EPI == 1) {
                        float2 f = __ldg((const float2*)(feat + (size_t)row * 128 + col));
                        v.x = fmaxf(v.x, 0.f) + f.x;
                        v.y = fmaxf(v.y, 0.f) + f.y;
                    }
                    *(float2*)(out + (size_t)row * 128 + col) = v;
                }
            }
        }

        if (!hasNext) break;

        // ---- convert + store prefetched tile into other buffer ------------
        {
            char* ab = sm + SM_A + (buf ^ 1) * A_STRIDE;
#pragma unroll
            for (int u = 0; u < 4; u++) {
                int idx = u * 512 + tid;
                int row = idx >> 6, p = idx & 63;
                float2 xv = xr[u];
                if (IN_RELU) { xv.x = fmaxf(xv.x, 0.f); xv.y = fmaxf(xv.y, 0.f); }
                float hx = __bfloat162float(__float2bfloat16_rn(xv.x));
                float hy = __bfloat162float(__float2bfloat16_rn(xv.y));
                uint32_t off = aswz2(row, p >> 2) + (p & 3) * 4;
                *(uint32_t*)(ab + off)        = pkbf(xv.x, xv.y);
                *(uint32_t*)(ab + A_LO + off) = pkbf(xv.x - hx, xv.y - hy);
            }
#pragma unroll
            for (int s2 = 0; s2 < 2; s2++) {
                int lr = wid * 2 + s2;
                float4 acc = ga[s2];
                uint32_t p0 = 64 + lane * 2;
                float hx = __bfloat162float(__float2bfloat16_rn(acc.x));
                float hy = __bfloat162float(__float2bfloat16_rn(acc.y));
                float hz = __bfloat162float(__float2bfloat16_rn(acc.z));
                float hw = __bfloat162float(__float2bfloat16_rn(acc.w));
                uint32_t off0 = aswz2(lr, p0 >> 2) + (p0 & 3) * 4;
                uint32_t off1 = aswz2(lr, (p0 + 1) >> 2) + ((p0 + 1) & 3) * 4;
                *(uint32_t*)(ab + off0)        = pkbf(acc.x, acc.y);
                *(uint32_t*)(ab + A_LO + off0) = pkbf(acc.x - hx, acc.y - hy);
                *(uint32_t*)(ab + off1)        = pkbf(acc.z, acc.w);
                *(uint32_t*)(ab + A_LO + off1) = pkbf(acc.z - hz, acc.w - hw);
            }
        }
        __syncthreads();
        tile = next;
        buf ^= 1;
    }
}

// ======================= fused final layer (dout=3) ========================
// out_i = h_i@W0 + (sum_j h_j)@W1 + b0 + deg_i*b1   (h already has relu+skip)
__global__ __launch_bounds__(256)
void final_fused_kernel(const float* __restrict__ h,
                        const int* __restrict__ rowstart,
                        const int* __restrict__ adj,
                        const int* __restrict__ deg,
                        const float* __restrict__ W0, const float* __restrict__ b0,
                        const float* __restrict__ W1, const float* __restrict__ b1,
                        float* __restrict__ out, int n)
{
    __shared__ float ws0[3][128];
    __shared__ float ws1[3][128];
    __shared__ float bb[8];
    int tid = threadIdx.x;
    for (int idx = tid; idx < 512; idx += 256) {   // FIX: 512 (was 384)
        int k = idx >> 2, c = idx & 3;             // k in 0..127, c<3 valid
        if (c < 3) {
            ws0[c][k] = __ldg(&W0[k * 3 + c]);
            ws1[c][k] = __ldg(&W1[k * 3 + c]);
        }
    }
    if (tid < 3) bb[tid] = __ldg(&b0[tid]);
    else if (tid < 6) bb[tid + 1] = __ldg(&b1[tid - 3]);   // bb[4..6]
    __syncthreads();

    int lane = tid & 31;
    int node = blockIdx.x * 8 + (tid >> 5);
    if (node >= n) return;

    int k0 = lane * 4;
    float4 xo = __ldg((const float4*)(h + (size_t)node * 128 + k0));

    float4 S = make_float4(0.f, 0.f, 0.f, 0.f);
    {
        int rs = __ldg(&rowstart[node]);
        int re = __ldg(&rowstart[node + 1]);
        int e = rs;
        for (; e + 3 < re; e += 4) {
            int j0 = __ldg(&adj[e]),     j1 = __ldg(&adj[e + 1]);
            int j2 = __ldg(&adj[e + 2]), j3 = __ldg(&adj[e + 3]);
            float4 v0 = __ldg((const float4*)(h + (size_t)j0 * 128 + k0));
            float4 v1 = __ldg((const float4*)(h + (size_t)j1 * 128 + k0));
            float4 v2 = __ldg((const float4*)(h + (size_t)j2 * 128 + k0));
            float4 v3 = __ldg((const float4*)(h + (size_t)j3 * 128 + k0));
            S.x += v0.x + v1.x + v2.x + v3.x;
            S.y += v0.y + v1.y + v2.y + v3.y;
            S.z += v0.z + v1.z + v2.z + v3.z;
            S.w += v0.w + v1.w + v2.w + v3.w;
        }
        for (; e < re; e++) {
            int j = __ldg(&adj[e]);
            float4 v = __ldg((const float4*)(h + (size_t)j * 128 + k0));
            S.x += v.x; S.y += v.y; S.z += v.z; S.w += v.w;
        }
    }

    float t[3];
#pragma unroll
    for (int c = 0; c < 3; c++) {
        float4 w0 = *(const float4*)&ws0[c][k0];
        float4 w1 = *(const float4*)&ws1[c][k0];
        t[c] = xo.x * w0.x + xo.y * w0.y + xo.z * w0.z + xo.w * w0.w
             + S.x * w1.x + S.y * w1.y + S.z * w1.z + S.w * w1.w;
    }
#pragma unroll
    for (int c = 0; c < 3; c++) {
#pragma unroll
        for (int o = 16; o > 0; o >>= 1)
            t[c] += __shfl_xor_sync(0xffffffffu, t[c], o);
    }
    if (lane == 0) {
        float dg = (float)__ldg(&deg[node]);
        out[node * 3 + 0] = t[0] + bb[0] + dg * bb[4];
        out[node * 3 + 1] = t[1] + bb[1] + dg * bb[5];
        out[node * 3 + 2] = t[2] + bb[2] + dg * bb[6];
    }
}

// ======================= launch ============================================
extern "C" void kernel_launch(void* const* d_in, const int* in_sizes, int n_in,
                              void* d_out, int out_size)
{
    const float* feat  = (const float*)d_in[0];
    const int2*  edges = (const int2*) d_in[1];
    const int N = in_sizes[0] / 128;
    const int E = in_sizes[1] / 2;

    const float *W0[4], *B0[4], *W1[4], *B1[4];
    for (int i = 0; i < 4; i++) {
        W0[i] = (const float*)d_in[2 + 4 * i];
        B0[i] = (const float*)d_in[3 + 4 * i];
        W1[i] = (const float*)d_in[4 + 4 * i];
        B1[i] = (const float*)d_in[5 + 4 * i];
    }

    float *bufA, *bufB, *biasAll;
    __nv_bfloat16 *whiAll, *wloAll;
    int *deg, *cur, *rowstart, *adj, *bsum;
    cudaGetSymbolAddress((void**)&bufA, g_bufA);
    cudaGetSymbolAddress((void**)&bufB, g_bufB);
    cudaGetSymbolAddress((void**)&whiAll, g_Whi);
    cudaGetSymbolAddress((void**)&wloAll, g_Wlo);
    cudaGetSymbolAddress((void**)&biasAll, g_bias);
    cudaGetSymbolAddress((void**)&deg, g_deg);
    cudaGetSymbolAddress((void**)&cur, g_cur);
    cudaGetSymbolAddress((void**)&rowstart, g_rowstart);
    cudaGetSymbolAddress((void**)&adj, g_adj);
    cudaGetSymbolAddress((void**)&bsum, g_bsum);

    cudaFuncSetAttribute(layer_fused_kernel<0,0>, cudaFuncAttributeMaxDynamicSharedMemorySize, SM_DYN);
    cudaFuncSetAttribute(layer_fused_kernel<1,0>, cudaFuncAttributeMaxDynamicSharedMemorySize, SM_DYN);
    cudaFuncSetAttribute(layer_fused_kernel<1,1>, cudaFuncAttributeMaxDynamicSharedMemorySize, SM_DYN);

    // weight prep (K=256 concat images)
    for (int l = 0; l < 3; l++) {
        prep_w_kernel<<<16, 256>>>(W0[l], B0[l], W1[l], B1[l],
                                   whiAll + l * 128 * 256, wloAll + l * 128 * 256,
                                   biasAll + l * 256);
    }

    // CSR build
    const int NB = (N + 1023) / 1024;
    zero_deg_kernel<<<(N + 255) / 256, 256>>>(deg, N);
    count_deg_kernel<<<(E + 255) / 256, 256>>>(edges, deg, E);
    scanA_kernel<<<NB, 1024>>>(deg, rowstart, bsum, N);
    scanB_kernel<<<1, 512>>>(bsum, NB);
    scanC_kernel<<<NB, 1024>>>(rowstart, cur, bsum, N, 2 * E);
    fill_adj_kernel<<<(E + 255) / 256, 256>>>(edges, cur, adj, E);

    const int numTiles = (N + 31) / 32;
    const int PGRID = 148;
    float* out = (float*)d_out;

    // layer 0: raw input
    layer_fused_kernel<0,0><<<PGRID, 512, SM_DYN>>>(feat, feat,
        whiAll, wloAll, biasAll, rowstart, adj, deg, bufA, N, numTiles);
    // layer 1: relu input
    layer_fused_kernel<1,0><<<PGRID, 512, SM_DYN>>>(bufA, feat,
        whiAll + 128 * 256, wloAll + 128 * 256, biasAll + 256,
        rowstart, adj, deg, bufB, N, numTiles);
    // layer 2: relu input, epilogue writes h = relu(out)+feat
    layer_fused_kernel<1,1><<<PGRID, 512, SM_DYN>>>(bufB, feat,
        whiAll + 2 * 128 * 256, wloAll + 2 * 128 * 256, biasAll + 2 * 256,
        rowstart, adj, deg, bufA, N, numTiles);
    // final layer: fused gather + dot (dout=3), writes d_out directly
    final_fused_kernel<<<(N + 7) / 8, 256>>>(bufA, rowstart, adj, deg,
        W0[3], B0[3], W1[3], B1[3], out, N);
}